// round 16
// baseline (speedup 1.0000x reference)
#include <cuda_runtime.h>
#include <math.h>

__device__ double g_sum = 0.0;

#define FULLM 0xFFFFFFFFu
#define IC 4   // vertically-stacked cells per thread (576 blocks: ~3.9/SM)

struct V3 { float x, y, z; };

__device__ __forceinline__ V3 ld3(const float* __restrict__ p) { return {p[0], p[1], p[2]}; }
__device__ __forceinline__ V3 vsub(V3 a, V3 b) { return {a.x - b.x, a.y - b.y, a.z - b.z}; }
__device__ __forceinline__ float vdot(V3 a, V3 b) { return a.x * b.x + a.y * b.y + a.z * b.z; }
__device__ __forceinline__ V3 vcross(V3 a, V3 b) {
    return {a.y * b.z - a.z * b.y,
            a.z * b.x - a.x * b.z,
            a.x * b.y - a.y * b.x};
}
__device__ __forceinline__ V3 face_normal(const float* __restrict__ q) {
    V3 t0 = ld3(q), t1 = ld3(q + 3), t2 = ld3(q + 6);
    V3 c = vcross(vsub(t0, t1), vsub(t0, t2));
    float s = rsqrtf(vdot(c, c));
    return {c.x * s, c.y * s, c.z * s};
}
__device__ __forceinline__ float tri_area(V3 p1, V3 p2, V3 p3) {
    V3 c = vcross(vsub(p2, p1), vsub(p3, p1));
    return 0.5f * sqrtf(vdot(c, c));
}

// Closed form of (pair*coeff).sum()/9 with x = na@(r1-r2), y = nb@(r1-r2).
// r1/r2 may be global pointers or register-resident local arrays.
__device__ __forceinline__ float edge_term(
    V3 u, V3 w, V3 na, V3 nb,
    const float* r1, const float* r2,
    float dv2, float asum)
{
    V3 x = {0, 0, 0}, y = {0, 0, 0};
    #pragma unroll
    for (int c = 0; c < 3; c++) {
        float d0 = r1[3 * c + 0] - r2[3 * c + 0];
        float d1 = r1[3 * c + 1] - r2[3 * c + 1];
        float d2 = r1[3 * c + 2] - r2[3 * c + 2];
        float ac = (c == 0) ? na.x : ((c == 1) ? na.y : na.z);
        float bc = (c == 0) ? nb.x : ((c == 1) ? nb.y : nb.z);
        x.x += ac * d0; x.y += ac * d1; x.z += ac * d2;
        y.x += bc * d0; y.y += bc * d1; y.z += bc * d2;
    }
    float en = (3.0f * (vdot(u, u) + vdot(w, w) + vdot(u, w))
              + vdot(x, x) + vdot(y, y) + vdot(x, y)) * (1.0f / 9.0f);
    return en * (dv2 / asum);
}

// IC vertically-stacked cells per thread, rolling boundary state in registers:
// verts rows (pT<-pB<-pC), tp[tri1(i+1,j)] rows 1-2 (loaded for the horizontal
// edge, become next cell's t1), n11 -> next n01, aD -> next aT1.
// rot[tri2] is loaded ONCE per cell into registers (used by all 3 edges).
// Per cell, up to 3 interior edges (diag always; horiz if i<m-1; vert if j<m-1).
// tri1(i,j)=i*m+j, tri2(i,j)=m*m+i*m+j (m=n-1). Edge-endpoint "normals" come
// from tp[vertex_id] (reference indexes normals by vertex ids).
__global__ __launch_bounds__(256, 4)
void k_cell(const float* __restrict__ tp,     // (F,3,3)
            const float* __restrict__ rot,    // (F,3,3)
            const float* __restrict__ verts,  // (V,3)
            int n)
{
    const int m  = n - 1;
    const int j  = blockIdx.x * blockDim.x + threadIdx.x;
    const int i0 = blockIdx.y * IC;
    float val = 0.0f;

    if (j < m) {
        const bool vertE = (j < m - 1);

        // ---- prologue: state for cell (i0, j) ----
        int i = i0;
        V3 pT0 = ld3(verts + 3 * (size_t)(i * n + j));
        V3 pT1 = ld3(verts + 3 * (size_t)(i * n + j + 1));
        V3 pB0 = ld3(verts + 3 * (size_t)((i + 1) * n + j));
        V3 pB1 = ld3(verts + 3 * (size_t)((i + 1) * n + j + 1));

        const float* q1 = tp + 9 * (size_t)(i * m + j);
        V3 t1_1 = ld3(q1 + 3), t1_2 = ld3(q1 + 6);   // row 0 of tri1 never used

        V3 n10 = face_normal(tp + 9 * (size_t)((i + 1) * n + j));
        V3 n01 = face_normal(tp + 9 * (size_t)(i * n + j + 1));
        V3 n11 = face_normal(tp + 9 * (size_t)((i + 1) * n + j + 1));

        const float* r1 = rot + 9 * (size_t)(i * m + j);
        float aT1 = tri_area(pT0, pB0, pT1);

        #pragma unroll
        for (int s = 0; s < IC; s++, i++) {
            if (i >= m) break;

            const int fT2 = m * m + i * m + j;
            const float* q2 = tp + 9 * (size_t)fT2;
            V3 t2_0 = ld3(q2), t2_1 = ld3(q2 + 3), t2_2 = ld3(q2 + 6);

            // rot[tri2]: load once into registers; consumed by all 3 edges
            float R2[9];
            {
                const float* r2g = rot + 9 * (size_t)fT2;
                #pragma unroll
                for (int c = 0; c < 9; c++) R2[c] = r2g[c];
            }

            float aT2 = tri_area(pB0, pB1, pT1);

            // diagonal edge (v10, v01)
            {
                V3 u = vsub(t1_1, t2_0), w = vsub(t1_2, t2_2), d = vsub(pB0, pT1);
                val += edge_term(u, w, n10, n01, r1, R2, vdot(d, d), aT1 + aT2);
            }
            // vertical edge (v11, v01) vs tri1(i, j+1)
            if (vertE) {
                const float* qr = tp + 9 * (size_t)(i * m + j + 1);
                V3 tr_0 = ld3(qr), tr_1 = ld3(qr + 3);
                V3 pT2 = ld3(verts + 3 * (size_t)(i * n + j + 2));
                float aR = tri_area(pT1, pB1, pT2);
                V3 u = vsub(t2_1, tr_1), w = vsub(t2_2, tr_0), d = vsub(pB1, pT1);
                val += edge_term(u, w, n11, n01, R2, rot + 9 * (size_t)(i * m + j + 1),
                                 vdot(d, d), aT2 + aR);
            }
            // horizontal edge (v10, v11) vs tri1(i+1, j)  [also rolls state]
            if (i < m - 1) {
                const int fD = (i + 1) * m + j;
                const float* qd = tp + 9 * (size_t)fD;
                V3 td_0 = ld3(qd), td_1 = ld3(qd + 3), td_2 = ld3(qd + 6);
                V3 pC0 = ld3(verts + 3 * (size_t)((i + 2) * n + j));
                V3 pC1 = ld3(verts + 3 * (size_t)((i + 2) * n + j + 1));
                float aD = tri_area(pB0, pC0, pB1);
                V3 u = vsub(t2_0, td_0), w = vsub(t2_1, td_2), d = vsub(pB0, pB1);
                val += edge_term(u, w, n10, n11, R2, rot + 9 * (size_t)fD,
                                 vdot(d, d), aT2 + aD);

                if (s + 1 < IC) {   // roll boundary state into next cell
                    pT0 = pB0; pT1 = pB1;
                    pB0 = pC0; pB1 = pC1;
                    t1_1 = td_1; t1_2 = td_2;
                    n01 = n11;
                    n10 = face_normal(tp + 9 * (size_t)((i + 2) * n + j));
                    n11 = face_normal(tp + 9 * (size_t)((i + 2) * n + j + 1));
                    r1  = rot + 9 * (size_t)fD;
                    aT1 = aD;
                }
            }
        }
    }

    // ---- warp reduce (fp32) -> cross-warp (fp64) -> one atomic per block ----
    #pragma unroll
    for (int off = 16; off > 0; off >>= 1)
        val += __shfl_down_sync(FULLM, val, off);

    __shared__ double sh[8];
    int lane = threadIdx.x & 31;
    int wid  = threadIdx.x >> 5;
    if (lane == 0) sh[wid] = (double)val;
    __syncthreads();
    if (threadIdx.x == 0) {
        double bsum = 0.0;
        #pragma unroll
        for (int w = 0; w < 8; w++) bsum += sh[w];
        atomicAdd(&g_sum, bsum);
    }
}

// Write result and reset accumulator for the next graph replay.
__global__ void k_fin(float* __restrict__ out) {
    out[0] = (float)g_sum;
    g_sum = 0.0;
}

extern "C" void kernel_launch(void* const* d_in, const int* in_sizes, int n_in,
                              void* d_out, int out_size)
{
    const float* tp    = (const float*)d_in[0];   // (F,3,3)
    const float* rot   = (const float*)d_in[1];   // (F,3,3)
    const float* verts = (const float*)d_in[2];   // (1,V,3)

    int V = in_sizes[2] / 3;
    int n = (int)(sqrt((double)V) + 0.5);
    int m = n - 1;

    dim3 block(256, 1, 1);
    dim3 grid((m + 255) / 256, (m + IC - 1) / IC, 1);

    k_cell<<<grid, block>>>(tp, rot, verts, n);
    k_fin<<<1, 1>>>((float*)d_out);
}

// round 17
// speedup vs baseline: 1.0145x; 1.0145x over previous
#include <cuda_runtime.h>
#include <math.h>

__device__ double g_sum = 0.0;

#define FULLM 0xFFFFFFFFu
#define IC 4   // vertically-stacked cells per thread (576 blocks: ~3.9/SM)

struct V3 { float x, y, z; };

__device__ __forceinline__ V3 ld3(const float* __restrict__ p) { return {p[0], p[1], p[2]}; }
__device__ __forceinline__ V3 vsub(V3 a, V3 b) { return {a.x - b.x, a.y - b.y, a.z - b.z}; }
__device__ __forceinline__ float vdot(V3 a, V3 b) { return a.x * b.x + a.y * b.y + a.z * b.z; }
__device__ __forceinline__ V3 vcross(V3 a, V3 b) {
    return {a.y * b.z - a.z * b.y,
            a.z * b.x - a.x * b.z,
            a.x * b.y - a.y * b.x};
}
__device__ __forceinline__ V3 face_normal(const float* __restrict__ q) {
    V3 t0 = ld3(q), t1 = ld3(q + 3), t2 = ld3(q + 6);
    V3 c = vcross(vsub(t0, t1), vsub(t0, t2));
    float s = rsqrtf(vdot(c, c));
    return {c.x * s, c.y * s, c.z * s};
}
__device__ __forceinline__ float tri_area(V3 p1, V3 p2, V3 p3) {
    V3 c = vcross(vsub(p2, p1), vsub(p3, p1));
    return 0.5f * sqrtf(vdot(c, c));
}

// Closed form of (pair*coeff).sum()/9 with x = na@(r1-r2), y = nb@(r1-r2).
__device__ __forceinline__ float edge_term(
    V3 u, V3 w, V3 na, V3 nb,
    const float* __restrict__ r1, const float* __restrict__ r2,
    float dv2, float asum)
{
    V3 x = {0, 0, 0}, y = {0, 0, 0};
    #pragma unroll
    for (int c = 0; c < 3; c++) {
        float d0 = r1[3 * c + 0] - r2[3 * c + 0];
        float d1 = r1[3 * c + 1] - r2[3 * c + 1];
        float d2 = r1[3 * c + 2] - r2[3 * c + 2];
        float ac = (c == 0) ? na.x : ((c == 1) ? na.y : na.z);
        float bc = (c == 0) ? nb.x : ((c == 1) ? nb.y : nb.z);
        x.x += ac * d0; x.y += ac * d1; x.z += ac * d2;
        y.x += bc * d0; y.y += bc * d1; y.z += bc * d2;
    }
    float en = (3.0f * (vdot(u, u) + vdot(w, w) + vdot(u, w))
              + vdot(x, x) + vdot(y, y) + vdot(x, y)) * (1.0f / 9.0f);
    return en * (dv2 / asum);
}

// IC vertically-stacked cells per thread, rolling boundary state in registers
// (measured-best body, R13). Per cell, up to 3 interior edges.
// tri1(i,j)=i*m+j, tri2(i,j)=m*m+i*m+j (m=n-1). Edge-endpoint "normals" come
// from tp[vertex_id] (reference indexes normals by vertex ids).
__global__ __launch_bounds__(256, 4)
void k_cell(const float* __restrict__ tp,     // (F,3,3)
            const float* __restrict__ rot,    // (F,3,3)
            const float* __restrict__ verts,  // (V,3)
            int n)
{
    const int m  = n - 1;
    const int j  = blockIdx.x * blockDim.x + threadIdx.x;
    const int i0 = blockIdx.y * IC;
    float val = 0.0f;

    if (j < m) {
        const bool vertE = (j < m - 1);

        // ---- prologue: state for cell (i0, j) ----
        int i = i0;
        V3 pT0 = ld3(verts + 3 * (size_t)(i * n + j));
        V3 pT1 = ld3(verts + 3 * (size_t)(i * n + j + 1));
        V3 pB0 = ld3(verts + 3 * (size_t)((i + 1) * n + j));
        V3 pB1 = ld3(verts + 3 * (size_t)((i + 1) * n + j + 1));

        const float* q1 = tp + 9 * (size_t)(i * m + j);
        V3 t1_1 = ld3(q1 + 3), t1_2 = ld3(q1 + 6);
        V3 t1_0 = ld3(q1);

        V3 n10 = face_normal(tp + 9 * (size_t)((i + 1) * n + j));
        V3 n01 = face_normal(tp + 9 * (size_t)(i * n + j + 1));
        V3 n11 = face_normal(tp + 9 * (size_t)((i + 1) * n + j + 1));

        const float* r1 = rot + 9 * (size_t)(i * m + j);
        float aT1 = tri_area(pT0, pB0, pT1);

        #pragma unroll
        for (int s = 0; s < IC; s++, i++) {
            if (i >= m) break;

            const int fT2 = m * m + i * m + j;
            const float* q2 = tp  + 9 * (size_t)fT2;
            const float* r2 = rot + 9 * (size_t)fT2;
            V3 t2_0 = ld3(q2), t2_1 = ld3(q2 + 3), t2_2 = ld3(q2 + 6);

            float aT2 = tri_area(pB0, pB1, pT1);

            // diagonal edge (v10, v01)
            {
                V3 u = vsub(t1_1, t2_0), w = vsub(t1_2, t2_2), d = vsub(pB0, pT1);
                val += edge_term(u, w, n10, n01, r1, r2, vdot(d, d), aT1 + aT2);
            }
            // vertical edge (v11, v01) vs tri1(i, j+1)
            if (vertE) {
                const float* qr = tp + 9 * (size_t)(i * m + j + 1);
                V3 tr_0 = ld3(qr), tr_1 = ld3(qr + 3);
                V3 pT2 = ld3(verts + 3 * (size_t)(i * n + j + 2));
                float aR = tri_area(pT1, pB1, pT2);
                V3 u = vsub(t2_1, tr_1), w = vsub(t2_2, tr_0), d = vsub(pB1, pT1);
                val += edge_term(u, w, n11, n01, r2, rot + 9 * (size_t)(i * m + j + 1),
                                 vdot(d, d), aT2 + aR);
            }
            // horizontal edge (v10, v11) vs tri1(i+1, j)  [also rolls state]
            if (i < m - 1) {
                const int fD = (i + 1) * m + j;
                const float* qd = tp + 9 * (size_t)fD;
                V3 td_0 = ld3(qd), td_1 = ld3(qd + 3), td_2 = ld3(qd + 6);
                V3 pC0 = ld3(verts + 3 * (size_t)((i + 2) * n + j));
                V3 pC1 = ld3(verts + 3 * (size_t)((i + 2) * n + j + 1));
                float aD = tri_area(pB0, pC0, pB1);
                V3 u = vsub(t2_0, td_0), w = vsub(t2_1, td_2), d = vsub(pB0, pB1);
                val += edge_term(u, w, n10, n11, r2, rot + 9 * (size_t)fD,
                                 vdot(d, d), aT2 + aD);

                if (s + 1 < IC) {   // roll boundary state into next cell
                    pT0 = pB0; pT1 = pB1;
                    pB0 = pC0; pB1 = pC1;
                    t1_0 = td_0; t1_1 = td_1; t1_2 = td_2;
                    n01 = n11;
                    n10 = face_normal(tp + 9 * (size_t)((i + 2) * n + j));
                    n11 = face_normal(tp + 9 * (size_t)((i + 2) * n + j + 1));
                    r1  = rot + 9 * (size_t)fD;
                    aT1 = aD;
                }
            }
        }
    }

    // ---- warp reduce (fp32) -> cross-warp (fp64) -> one atomic per block ----
    #pragma unroll
    for (int off = 16; off > 0; off >>= 1)
        val += __shfl_down_sync(FULLM, val, off);

    __shared__ double sh[8];
    int lane = threadIdx.x & 31;
    int wid  = threadIdx.x >> 5;
    if (lane == 0) sh[wid] = (double)val;
    __syncthreads();
    if (threadIdx.x == 0) {
        double bsum = 0.0;
        #pragma unroll
        for (int w = 0; w < 8; w++) bsum += sh[w];
        atomicAdd(&g_sum, bsum);
    }
}

// Finalize: launched with programmatic dependent launch (PDL) so its setup
// overlaps k_cell's drain. We never call the trigger in k_cell, so
// cudaGridDependencySynchronize() waits for FULL k_cell completion (all
// g_sum atomics visible) before we read.
__global__ void k_fin(float* __restrict__ out) {
    cudaGridDependencySynchronize();
    out[0] = (float)g_sum;
    g_sum = 0.0;   // self-reset -> graph-replay safe
}

extern "C" void kernel_launch(void* const* d_in, const int* in_sizes, int n_in,
                              void* d_out, int out_size)
{
    const float* tp    = (const float*)d_in[0];   // (F,3,3)
    const float* rot   = (const float*)d_in[1];   // (F,3,3)
    const float* verts = (const float*)d_in[2];   // (1,V,3)

    int V = in_sizes[2] / 3;
    int n = (int)(sqrt((double)V) + 0.5);
    int m = n - 1;

    dim3 block(256, 1, 1);
    dim3 grid((m + 255) / 256, (m + IC - 1) / IC, 1);

    k_cell<<<grid, block>>>(tp, rot, verts, n);

    // PDL launch of the finalizer: overlap its launch latency with k_cell.
    cudaLaunchConfig_t cfg = {};
    cfg.gridDim  = dim3(1, 1, 1);
    cfg.blockDim = dim3(1, 1, 1);
    cfg.dynamicSmemBytes = 0;
    cfg.stream = 0;   // legacy default stream (same as <<<>>> above)
    cudaLaunchAttribute attr[1];
    attr[0].id = cudaLaunchAttributeProgrammaticStreamSerialization;
    attr[0].val.programmaticStreamSerializationAllowed = 1;
    cfg.attrs = attr;
    cfg.numAttrs = 1;
    cudaLaunchKernelEx(&cfg, k_fin, (float*)d_out);
}